// round 1
// baseline (speedup 1.0000x reference)
#include <cuda_runtime.h>
#include <cstdint>
#include <cstdio>

#define NUM_EMBEDS 8192
#define EMBED_DIM  256
#define BATCH      16
#define TLEN       1024
#define NVEC       (BATCH * TLEN)            /* 16384 */
#define ZQ_ELEMS   (BATCH * EMBED_DIM * TLEN) /* 4194304 */

/* ---- scratch (no allocations allowed; __device__ globals) ---- */
__device__ float g_cnorm[NUM_EMBEDS];
__device__ int   g_idx[NVEC];
__device__ int   g_counts[NUM_EMBEDS];
__device__ float g_loss_part[256];

/* ================= prep: codebook norms + zero histogram ================= */
__global__ void prep_kernel(const float* __restrict__ codebook) {
    int c = blockIdx.x;                 // 8192 blocks, 32 threads
    const float4* row = (const float4*)(codebook + (size_t)c * EMBED_DIM);
    float s = 0.f;
    for (int i = threadIdx.x; i < EMBED_DIM / 4; i += 32) {
        float4 q = row[i];
        s += q.x * q.x + q.y * q.y + q.z * q.z + q.w * q.w;
    }
#pragma unroll
    for (int o = 16; o; o >>= 1) s += __shfl_down_sync(0xffffffffu, s, o);
    if (threadIdx.x == 0) {
        g_cnorm[c] = s;
        g_counts[c] = 0;
    }
}

/* ================= main argmin kernel =================
 * 64 rows/block, codes streamed in 256-wide chunks, d staged 32 at a time.
 * Thread tile: 8 rows x 8 cols, rows packed as f32x2 pairs.
 */
#define TM   64
#define TNC  256
#define DKC  32
#define XW   66          /* Xs row stride (floats): [256][66] */
#define CW   260         /* Cs row stride (floats): [32][260] */
#define SMEM_BYTES ((256 * XW + DKC * CW) * 4)   /* 100864 B */

__global__ __launch_bounds__(256, 2)
void argmin_kernel(const float* __restrict__ z_e,
                   const float* __restrict__ codebook) {
    extern __shared__ float smem[];
    float* Xs = smem;              // [256][XW]  transposed z_e tile
    float* Cs = smem + 256 * XW;   // [DKC][CW]  transposed codebook stage

    int tid = threadIdx.x;
    int n0  = blockIdx.x * TM;
    int b   = n0 >> 10;
    int t0  = n0 & 1023;
    const float* zeb = z_e + (size_t)b * EMBED_DIM * TLEN + t0;

    /* stage X transposed: Xs[d][tt] = z_e[b, d, t0+tt]  (coalesced gmem) */
    {
        int tt = tid & 63, dd = tid >> 6;  // dd in 0..3
        for (int d = dd; d < EMBED_DIM; d += 4)
            Xs[d * XW + tt] = zeb[(size_t)d * TLEN + tt];
    }

    int tx = tid & 31;   // col lane: codes tx + 32*j
    int ry = tid >> 5;   // row group: rows ry*8 .. ry*8+7
    const float* Xp = Xs + ry * 8;
    const float* Cp = Cs + tx;

    float bestv[8];
    int   besti[8];
#pragma unroll
    for (int i = 0; i < 8; ++i) { bestv[i] = 3.4e38f; besti[i] = 0; }

    const float4* cb4 = (const float4*)codebook;

    for (int k0 = 0; k0 < NUM_EMBEDS; k0 += TNC) {
        unsigned long long acc[4][8];
#pragma unroll
        for (int i = 0; i < 4; ++i)
#pragma unroll
            for (int j = 0; j < 8; ++j) acc[i][j] = 0ULL;

        for (int d0 = 0; d0 < EMBED_DIM; d0 += DKC) {
            __syncthreads();
            /* stage Cs transposed: Cs[dd][c] = codebook[k0+c][d0+dd] */
#pragma unroll
            for (int it = 0; it < 8; ++it) {
                int v  = tid + 256 * it;   // 0..2047
                int d4 = v & 7;            // quad index within 32 d's
                int c  = v >> 3;           // 0..255
                float4 q = cb4[(size_t)(k0 + c) * (EMBED_DIM / 4) + (d0 >> 2) + d4];
                float* dst = Cs + (4 * d4) * CW + c;
                dst[0 * CW] = q.x;
                dst[1 * CW] = q.y;
                dst[2 * CW] = q.z;
                dst[3 * CW] = q.w;
            }
            __syncthreads();

#pragma unroll 4
            for (int dd = 0; dd < DKC; ++dd) {
                int d = d0 + dd;
                const float* xrow = Xp + d * XW;
                unsigned long long x0 = *(const unsigned long long*)(xrow + 0);
                unsigned long long x1 = *(const unsigned long long*)(xrow + 2);
                unsigned long long x2 = *(const unsigned long long*)(xrow + 4);
                unsigned long long x3 = *(const unsigned long long*)(xrow + 6);
                const float* crow = Cp + dd * CW;
#pragma unroll
                for (int j = 0; j < 8; ++j) {
                    unsigned int cu = __float_as_uint(crow[32 * j]);
                    unsigned long long c2;
                    asm("mov.b64 %0, {%1, %1};" : "=l"(c2) : "r"(cu));
                    asm("fma.rn.f32x2 %0, %1, %2, %0;" : "+l"(acc[0][j]) : "l"(x0), "l"(c2));
                    asm("fma.rn.f32x2 %0, %1, %2, %0;" : "+l"(acc[1][j]) : "l"(x1), "l"(c2));
                    asm("fma.rn.f32x2 %0, %1, %2, %0;" : "+l"(acc[2][j]) : "l"(x2), "l"(c2));
                    asm("fma.rn.f32x2 %0, %1, %2, %0;" : "+l"(acc[3][j]) : "l"(x3), "l"(c2));
                }
            }
        }

        /* epilogue: dist = ||c||^2 - 2*dot (||x||^2 constant per row) */
#pragma unroll
        for (int j = 0; j < 8; ++j) {
            int code = k0 + tx + 32 * j;
            float cn = g_cnorm[code];
#pragma unroll
            for (int i2 = 0; i2 < 4; ++i2) {
                float lo = __uint_as_float((unsigned)(acc[i2][j] & 0xffffffffULL));
                float hi = __uint_as_float((unsigned)(acc[i2][j] >> 32));
                float dl = fmaf(-2.f, lo, cn);
                float dh = fmaf(-2.f, hi, cn);
                int r0 = 2 * i2, r1 = 2 * i2 + 1;
                if (dl < bestv[r0]) { bestv[r0] = dl; besti[r0] = code; }
                if (dh < bestv[r1]) { bestv[r1] = dh; besti[r1] = code; }
            }
        }
    }

    /* cross-lane argmin per row (32 lanes hold disjoint code subsets) */
#pragma unroll
    for (int i = 0; i < 8; ++i) {
        float v = bestv[i];
        int  id = besti[i];
        for (int o = 16; o; o >>= 1) {
            float ov = __shfl_down_sync(0xffffffffu, v, o);
            int   oi = __shfl_down_sync(0xffffffffu, id, o);
            if (ov < v || (ov == v && oi < id)) { v = ov; id = oi; }
        }
        if (tx == 0) g_idx[n0 + ry * 8 + i] = id;
    }
}

/* ================= gather z_q, loss partials, histogram ================= */
__global__ __launch_bounds__(256)
void gather_kernel(const float* __restrict__ z_e,
                   const float* __restrict__ codebook,
                   float* __restrict__ out) {
    __shared__ int   sidx[64];
    __shared__ float red[256];
    int tid = threadIdx.x;
    int n0  = blockIdx.x * 64;
    if (tid < 64) sidx[tid] = g_idx[n0 + tid];
    __syncthreads();
    if (tid < 64) atomicAdd(&g_counts[sidx[tid]], 1);

    int tt = tid & 63, dd = tid >> 6;
    int b = n0 >> 10, t0 = n0 & 1023;
    size_t base = (size_t)b * EMBED_DIM * TLEN + t0 + tt;
    const float* crow = codebook + (size_t)sidx[tt] * EMBED_DIM;

    float local = 0.f;
    for (int d = dd; d < EMBED_DIM; d += 4) {
        float q = __ldg(crow + d);
        size_t a = base + (size_t)d * TLEN;
        float ze = z_e[a];
        out[a] = q;                         // coalesced (t contiguous per warp)
        float df = q - ze;
        local = fmaf(df, df, local);
    }
    red[tid] = local;
    __syncthreads();
    for (int s = 128; s > 0; s >>= 1) {
        if (tid < s) red[tid] += red[tid + s];
        __syncthreads();
    }
    if (tid == 0) g_loss_part[blockIdx.x] = red[0];
}

/* ================= finalize scalars ================= */
__global__ void finalize_kernel(float* __restrict__ out) {
    __shared__ float red[256];
    int tid = threadIdx.x;

    red[tid] = g_loss_part[tid];
    __syncthreads();
    for (int s = 128; s > 0; s >>= 1) {
        if (tid < s) red[tid] += red[tid + s];
        __syncthreads();
    }
    if (tid == 0)
        out[ZQ_ELEMS] = red[0] / (float)ZQ_ELEMS;   /* ALPHA=1, (1-b)q+b e == mean */
    __syncthreads();

    float sl = 0.f;
    for (int c = tid; c < NUM_EMBEDS; c += 256) {
        float p = (float)g_counts[c] * (1.f / (float)NVEC);
        sl += p * logf(p + 1e-10f);
    }
    red[tid] = sl;
    __syncthreads();
    for (int s = 128; s > 0; s >>= 1) {
        if (tid < s) red[tid] += red[tid + s];
        __syncthreads();
    }
    if (tid == 0) out[ZQ_ELEMS + 1] = expf(-red[0]);
}

/* ================= launch ================= */
extern "C" void kernel_launch(void* const* d_in, const int* in_sizes, int n_in,
                              void* d_out, int out_size) {
    const float* z_e      = (const float*)d_in[0];
    const float* codebook = (const float*)d_in[1];
    float* out = (float*)d_out;

    cudaFuncSetAttribute(argmin_kernel,
                         cudaFuncAttributeMaxDynamicSharedMemorySize, SMEM_BYTES);

    prep_kernel<<<NUM_EMBEDS, 32>>>(codebook);
    argmin_kernel<<<NVEC / TM, 256, SMEM_BYTES>>>(z_e, codebook);
    gather_kernel<<<NVEC / 64, 256>>>(z_e, codebook, out);
    finalize_kernel<<<1, 256>>>(out);
}

// round 3
// speedup vs baseline: 4.1157x; 4.1157x over previous
#include <cuda_runtime.h>
#include <cuda_bf16.h>
#include <cstdint>

#define NUM_EMBEDS 8192
#define EMBED_DIM  256
#define BATCH      16
#define TLEN       1024
#define NVEC       (BATCH * TLEN)             /* 16384 */
#define ZQ_ELEMS   (BATCH * EMBED_DIM * TLEN) /* 4194304 */
#define CAP        64

/* ---- scratch (__device__ globals; no runtime allocs) ---- */
__device__ float          g_cnorm[NUM_EMBEDS];
__device__ float          g_xn2[NVEC];
__device__ float          g_wrow[NVEC];
__device__ int            g_cnmax_i;
__device__ unsigned       g_amin[NVEC];
__device__ int            g_ccount[NVEC];
__device__ int            g_cand[NVEC * CAP];
__device__ int            g_idx[NVEC];
__device__ int            g_counts[NUM_EMBEDS];
__device__ float          g_loss_part[256];
__device__ float          g_zet[NVEC * EMBED_DIM];              /* z_e transposed fp32 */
__device__ __nv_bfloat16  g_zbf[NVEC * EMBED_DIM];              /* z_e transposed bf16 */
__device__ __nv_bfloat16  g_cbf[NUM_EMBEDS * EMBED_DIM];        /* codebook bf16 */

/* ============================ helpers ============================ */
__device__ __forceinline__ uint32_t smem_u32(const void* p) {
    uint32_t a;
    asm("{ .reg .u64 t; cvta.to.shared.u64 t, %1; cvt.u32.u64 %0, t; }" : "=r"(a) : "l"(p));
    return a;
}
__device__ __forceinline__ unsigned enc_f(float f) {
    unsigned u = __float_as_uint(f);
    return (u & 0x80000000u) ? ~u : (u | 0x80000000u);
}
__device__ __forceinline__ float dec_f(unsigned u) {
    return (u & 0x80000000u) ? __uint_as_float(u ^ 0x80000000u) : __uint_as_float(~u);
}
__device__ __forceinline__ unsigned pack_bf2(float a, float b) {
    __nv_bfloat162 h = __floats2bfloat162_rn(a, b);
    return *(unsigned*)&h;
}

#define LDSM4(r, addr)                                                          \
    asm volatile("ldmatrix.sync.aligned.m8n8.x4.shared.b16 {%0,%1,%2,%3}, [%4];"\
        : "=r"((r)[0]), "=r"((r)[1]), "=r"((r)[2]), "=r"((r)[3]) : "r"(addr))

#define MMA_BF16(d, a, b)                                                       \
    asm volatile("mma.sync.aligned.m16n8k16.row.col.f32.bf16.bf16.f32 "         \
        "{%0,%1,%2,%3}, {%4,%5,%6,%7}, {%8,%9}, {%0,%1,%2,%3};"                 \
        : "+f"((d)[0]), "+f"((d)[1]), "+f"((d)[2]), "+f"((d)[3])                \
        : "r"((a)[0]), "r"((a)[1]), "r"((a)[2]), "r"((a)[3]),                   \
          "r"((b)[0]), "r"((b)[1]))

#define CP_ASYNC16(dst, src)                                                    \
    asm volatile("cp.async.cg.shared.global [%0], [%1], 16;" :: "r"(dst), "l"(src))
#define CP_COMMIT()  asm volatile("cp.async.commit_group;" ::: "memory")
#define CP_WAIT(n)   asm volatile("cp.async.wait_group %0;" :: "n"(n) : "memory")

/* ================= P0: init state ================= */
__global__ void init_kernel() {
    int i = blockIdx.x * 256 + threadIdx.x;   /* grid 64 x 256 = 16384 */
    g_xn2[i] = 0.f;
    g_amin[i] = 0xFFFFFFFFu;
    g_ccount[i] = 0;
    if (i < NUM_EMBEDS) g_counts[i] = 0;
    if (i == 0) g_cnmax_i = 0;
}

/* ================= P1: codebook -> bf16, cnorm, cnmax ================= */
__global__ __launch_bounds__(256)
void cb_prep_kernel(const float* __restrict__ codebook) {
    int lane = threadIdx.x & 31;
    int row  = blockIdx.x * 8 + (threadIdx.x >> 5);   /* grid 1024 */
    const float4* src = (const float4*)(codebook + (size_t)row * EMBED_DIM);
    float4 v0 = src[lane * 2], v1 = src[lane * 2 + 1];
    float s = v0.x*v0.x + v0.y*v0.y + v0.z*v0.z + v0.w*v0.w
            + v1.x*v1.x + v1.y*v1.y + v1.z*v1.z + v1.w*v1.w;
    uint4 u;
    u.x = pack_bf2(v0.x, v0.y); u.y = pack_bf2(v0.z, v0.w);
    u.z = pack_bf2(v1.x, v1.y); u.w = pack_bf2(v1.z, v1.w);
    ((uint4*)(g_cbf + (size_t)row * EMBED_DIM))[lane] = u;
#pragma unroll
    for (int o = 16; o; o >>= 1) s += __shfl_down_sync(0xffffffffu, s, o);
    if (lane == 0) {
        g_cnorm[row] = s;
        atomicMax(&g_cnmax_i, __float_as_int(s));
    }
}

/* ================= P2: z_e transpose (fp32 + bf16) + xnorm ================= */
__global__ __launch_bounds__(256)
void ze_prep_kernel(const float* __restrict__ z_e) {
    __shared__ float s[64][65];
    int n0 = blockIdx.x * 64;      /* grid.x = 256 */
    int d0 = blockIdx.y * 64;      /* grid.y = 4 */
    int b  = n0 >> 10, t0 = n0 & 1023;
    int tx = threadIdx.x & 63, ty = threadIdx.x >> 6;
    const float* src = z_e + ((size_t)b * EMBED_DIM + d0) * TLEN + t0;
#pragma unroll
    for (int j = 0; j < 16; ++j) {
        int dl = j * 4 + ty;
        s[dl][tx] = src[(size_t)dl * TLEN + tx];
    }
    __syncthreads();
#pragma unroll
    for (int j = 0; j < 16; ++j) {
        int nl = j * 4 + ty;
        float v = s[tx][nl];
        g_zet[(size_t)(n0 + nl) * EMBED_DIM + d0 + tx] = v;
        g_zbf[(size_t)(n0 + nl) * EMBED_DIM + d0 + tx] = __float2bfloat16_rn(v);
    }
    /* xnorm partial: thread (tx=token, ty=seg of 16 dims) */
    float p = 0.f;
#pragma unroll
    for (int j = 0; j < 16; ++j) {
        float v = s[ty * 16 + j][tx];
        p = fmaf(v, v, p);
    }
    atomicAdd(&g_xn2[n0 + tx], p);
}

/* ================= P3: per-row screening window ================= */
__global__ void wrow_kernel() {
    int i = blockIdx.x * 256 + threadIdx.x;   /* grid 64 */
    float cnmax = __int_as_float(g_cnmax_i);
    g_wrow[i] = 0.035f * sqrtf(g_xn2[i]) * sqrtf(cnmax) + 0.5f;
}

/* ================= K2: bf16 screening GEMM + candidate collection =================
 * CTA tile 128 rows x 256 codes, K=256 in 2 cp.async stages of 128.
 * 8 warps (2x4), warp tile 64x64, mma.sync m16n8k16 bf16.
 */
#define STR       136                       /* smem row stride in halves (272 B) */
#define A_STAGE   (128 * STR * 2)           /* 34816 B */
#define B_STAGE   (256 * STR * 2)           /* 69632 B */
#define SMEM_GEMM (2 * A_STAGE + 2 * B_STAGE)  /* 208896 B */

__global__ __launch_bounds__(256, 1)
void gemm_screen_kernel() {
    extern __shared__ char sm[];
    uint32_t sb = smem_u32(sm);
    int tid = threadIdx.x, lane = tid & 31, warp = tid >> 5;
    int wm = warp >> 2, wn = warp & 3;
    int bx = blockIdx.x;   /* row tile  (128) */
    int by = blockIdx.y;   /* code tile (32)  */

    const __nv_bfloat16* za = g_zbf + (size_t)(bx * 128) * EMBED_DIM;
    const __nv_bfloat16* cb = g_cbf + (size_t)(by * 256) * EMBED_DIM;

    /* prefetch both K stages */
#pragma unroll
    for (int s = 0; s < 2; ++s) {
        int ks = s * 128;
        uint32_t As = sb + s * A_STAGE;
        uint32_t Bs = sb + 2 * A_STAGE + s * B_STAGE;
#pragma unroll
        for (int q = 0; q < 8; ++q) {
            int v = tid + q * 256;          /* 0..2047 */
            int row = v >> 4, c = v & 15;
            CP_ASYNC16(As + (uint32_t)(row * STR + c * 8) * 2,
                       (const char*)(za + (size_t)row * EMBED_DIM + ks + c * 8));
        }
#pragma unroll
        for (int q = 0; q < 16; ++q) {
            int v = tid + q * 256;          /* 0..4095 */
            int row = v >> 4, c = v & 15;
            CP_ASYNC16(Bs + (uint32_t)(row * STR + c * 8) * 2,
                       (const char*)(cb + (size_t)row * EMBED_DIM + ks + c * 8));
        }
        CP_COMMIT();
    }

    float acc[4][8][4];
#pragma unroll
    for (int mi = 0; mi < 4; ++mi)
#pragma unroll
        for (int ni = 0; ni < 8; ++ni)
#pragma unroll
            for (int r = 0; r < 4; ++r) acc[mi][ni][r] = 0.f;

    int arow = lane & 15, acol = (lane >> 4) * 8;
    int bnl  = (lane & 7) + ((lane >> 4) & 1) * 8;
    int bkl  = ((lane >> 3) & 1) * 8;

    CP_WAIT(1);
    __syncthreads();
#pragma unroll
    for (int s = 0; s < 2; ++s) {
        if (s == 1) { CP_WAIT(0); __syncthreads(); }
        uint32_t As = sb + s * A_STAGE;
        uint32_t Bs = sb + 2 * A_STAGE + s * B_STAGE;
#pragma unroll
        for (int kk = 0; kk < 8; ++kk) {
            uint32_t a[4][4], bfr[8][2];
#pragma unroll
            for (int mi = 0; mi < 4; ++mi) {
                uint32_t addr = As + (uint32_t)((wm * 64 + mi * 16 + arow) * STR
                                                + acol + kk * 16) * 2;
                LDSM4(a[mi], addr);
            }
#pragma unroll
            for (int p = 0; p < 4; ++p) {
                uint32_t r4[4];
                uint32_t addr = Bs + (uint32_t)((wn * 64 + p * 16 + bnl) * STR
                                                + bkl + kk * 16) * 2;
                LDSM4(r4, addr);
                bfr[2*p][0] = r4[0]; bfr[2*p][1] = r4[1];
                bfr[2*p+1][0] = r4[2]; bfr[2*p+1][1] = r4[3];
            }
#pragma unroll
            for (int mi = 0; mi < 4; ++mi)
#pragma unroll
                for (int ni = 0; ni < 8; ++ni)
                    MMA_BF16(acc[mi][ni], a[mi], bfr[ni]);
        }
    }

    /* ---------- epilogue ---------- */
    int code0 = by * 256 + wn * 64 + 2 * (lane & 3);
    float cn[16];
#pragma unroll
    for (int ni = 0; ni < 8; ++ni) {
        cn[2*ni]   = g_cnorm[code0 + ni * 8];
        cn[2*ni+1] = g_cnorm[code0 + ni * 8 + 1];
    }

    /* row mins + atomicMin */
#pragma unroll
    for (int mi = 0; mi < 4; ++mi) {
#pragma unroll
        for (int h = 0; h < 2; ++h) {
            int row = bx * 128 + wm * 64 + mi * 16 + (lane >> 2) + h * 8;
            float m = 3.4e38f;
#pragma unroll
            for (int ni = 0; ni < 8; ++ni) {
                float d0 = fmaf(-2.f, acc[mi][ni][2*h],   cn[2*ni]);
                float d1 = fmaf(-2.f, acc[mi][ni][2*h+1], cn[2*ni+1]);
                m = fminf(m, fminf(d0, d1));
            }
            float o1 = __shfl_xor_sync(0xffffffffu, m, 1);  m = fminf(m, o1);
            float o2 = __shfl_xor_sync(0xffffffffu, m, 2);  m = fminf(m, o2);
            if ((lane & 3) == 0) atomicMin(&g_amin[row], enc_f(m));
        }
    }
    /* candidate append (superset-safe: threshold monotonically shrinks) */
#pragma unroll
    for (int mi = 0; mi < 4; ++mi) {
#pragma unroll
        for (int h = 0; h < 2; ++h) {
            int row = bx * 128 + wm * 64 + mi * 16 + (lane >> 2) + h * 8;
            float th = dec_f(*(volatile unsigned*)&g_amin[row]) + g_wrow[row];
#pragma unroll
            for (int ni = 0; ni < 8; ++ni) {
#pragma unroll
                for (int e = 0; e < 2; ++e) {
                    float d = fmaf(-2.f, acc[mi][ni][2*h + e], cn[2*ni + e]);
                    if (d <= th) {
                        int slot = atomicAdd(&g_ccount[row], 1);
                        if (slot < CAP)
                            g_cand[row * CAP + slot] = code0 + ni * 8 + e;
                    }
                }
            }
        }
    }
}

/* ================= K3: exact fp32 rescore of candidates ================= */
__global__ __launch_bounds__(256)
void rescore_kernel(const float* __restrict__ codebook) {
    int lane = threadIdx.x & 31;
    int row  = blockIdx.x * 8 + (threadIdx.x >> 5);   /* grid 2048 */
    int cnt  = g_ccount[row];

    const float4* zr = (const float4*)(g_zet + (size_t)row * EMBED_DIM);
    float4 z0 = zr[lane * 2], z1 = zr[lane * 2 + 1];

    float bv = 3.4e38f;
    int   bi = 0x7fffffff;
    int n_iter = (cnt <= CAP) ? cnt : NUM_EMBEDS;
    for (int i = 0; i < n_iter; ++i) {
        int code = (cnt <= CAP) ? g_cand[row * CAP + i] : i;
        const float4* cr = (const float4*)(codebook + (size_t)code * EMBED_DIM);
        float4 c0 = cr[lane * 2], c1 = cr[lane * 2 + 1];
        float d = z0.x*c0.x + z0.y*c0.y + z0.z*c0.z + z0.w*c0.w
                + z1.x*c1.x + z1.y*c1.y + z1.z*c1.z + z1.w*c1.w;
#pragma unroll
        for (int o = 16; o; o >>= 1) d += __shfl_xor_sync(0xffffffffu, d, o);
        float dist = fmaf(-2.f, d, g_cnorm[code]);
        if (dist < bv || (dist == bv && code < bi)) { bv = dist; bi = code; }
    }
    if (lane == 0) g_idx[row] = bi;
}

/* ================= K4: gather z_q, loss partials, histogram ================= */
__global__ __launch_bounds__(256)
void gather_kernel(const float* __restrict__ z_e,
                   const float* __restrict__ codebook,
                   float* __restrict__ out) {
    __shared__ int   sidx[64];
    __shared__ float red[256];
    int tid = threadIdx.x;
    int n0  = blockIdx.x * 64;
    if (tid < 64) sidx[tid] = g_idx[n0 + tid];
    __syncthreads();
    if (tid < 64) atomicAdd(&g_counts[sidx[tid]], 1);

    int tt = tid & 63, dd = tid >> 6;
    int b = n0 >> 10, t0 = n0 & 1023;
    size_t base = (size_t)b * EMBED_DIM * TLEN + t0 + tt;
    const float* crow = codebook + (size_t)sidx[tt] * EMBED_DIM;

    float local = 0.f;
    for (int d = dd; d < EMBED_DIM; d += 4) {
        float q = __ldg(crow + d);
        size_t a = base + (size_t)d * TLEN;
        float ze = z_e[a];
        out[a] = q;
        float df = q - ze;
        local = fmaf(df, df, local);
    }
    red[tid] = local;
    __syncthreads();
    for (int s = 128; s > 0; s >>= 1) {
        if (tid < s) red[tid] += red[tid + s];
        __syncthreads();
    }
    if (tid == 0) g_loss_part[blockIdx.x] = red[0];
}

/* ================= K5: finalize scalars ================= */
__global__ void finalize_kernel(float* __restrict__ out) {
    __shared__ float red[256];
    int tid = threadIdx.x;

    red[tid] = g_loss_part[tid];
    __syncthreads();
    for (int s = 128; s > 0; s >>= 1) {
        if (tid < s) red[tid] += red[tid + s];
        __syncthreads();
    }
    if (tid == 0)
        out[ZQ_ELEMS] = red[0] / (float)ZQ_ELEMS;
    __syncthreads();

    float sl = 0.f;
    for (int c = tid; c < NUM_EMBEDS; c += 256) {
        float p = (float)g_counts[c] * (1.f / (float)NVEC);
        sl += p * logf(p + 1e-10f);
    }
    red[tid] = sl;
    __syncthreads();
    for (int s = 128; s > 0; s >>= 1) {
        if (tid < s) red[tid] += red[tid + s];
        __syncthreads();
    }
    if (tid == 0) out[ZQ_ELEMS + 1] = expf(-red[0]);
}

/* ================= launch ================= */
extern "C" void kernel_launch(void* const* d_in, const int* in_sizes, int n_in,
                              void* d_out, int out_size) {
    const float* z_e      = (const float*)d_in[0];
    const float* codebook = (const float*)d_in[1];
    float* out = (float*)d_out;

    cudaFuncSetAttribute(gemm_screen_kernel,
                         cudaFuncAttributeMaxDynamicSharedMemorySize, SMEM_GEMM);

    init_kernel<<<64, 256>>>();
    cb_prep_kernel<<<NUM_EMBEDS / 8, 256>>>(codebook);
    ze_prep_kernel<<<dim3(NVEC / 64, EMBED_DIM / 64), 256>>>(z_e);
    wrow_kernel<<<NVEC / 256, 256>>>();
    gemm_screen_kernel<<<dim3(NVEC / 128, NUM_EMBEDS / 256), 256, SMEM_GEMM>>>();
    rescore_kernel<<<NVEC / 8, 256>>>(codebook);
    gather_kernel<<<NVEC / 64, 256>>>(z_e, codebook, out);
    finalize_kernel<<<1, 256>>>(out);
}